// round 2
// baseline (speedup 1.0000x reference)
#include <cuda_runtime.h>
#include <cstdint>
#include <cstdio>

#define HID 256
#define HS  512
#define NH  8
#define HD  64
#define NTOK 8
#define BB  8

// Per-batch folded query vectors: u[b][e][ch] = (sum_d qh[b,e,d]*w_kv[ch, e*128+d]) * rms_w[ch] * 0.125
__device__ float g_u[BB][NH][HID];

static __device__ __forceinline__ unsigned long long pk2(float lo, float hi){
  unsigned long long r; asm("mov.b64 %0, {%1,%2};" : "=l"(r) : "f"(lo), "f"(hi)); return r;
}
static __device__ __forceinline__ void upk2(unsigned long long v, float& lo, float& hi){
  asm("mov.b64 {%0,%1}, %2;" : "=f"(lo), "=f"(hi) : "l"(v));
}
static __device__ __forceinline__ unsigned long long f2fma(unsigned long long a, unsigned long long b, unsigned long long c){
  unsigned long long d; asm("fma.rn.f32x2 %0, %1, %2, %3;" : "=l"(d) : "l"(a), "l"(b), "l"(c)); return d;
}

// ---------------- setup: qh = silu(emb[q]@w1+b1)@w2+b2 ; u = (w_kv_k,e @ qh_e) * rms_w * scale
__global__ void setup_kernel(const int* __restrict__ q, const float* __restrict__ emb,
                             const float* __restrict__ w1, const float* __restrict__ b1,
                             const float* __restrict__ w2, const float* __restrict__ b2,
                             const float* __restrict__ w_kv, const float* __restrict__ rms_w)
{
  __shared__ float qe[HID], s1[HS], qh[HS];
  int b = blockIdx.x, t = threadIdx.x;
  if (t < HID) qe[t] = emb[(size_t)q[b]*HID + t];
  __syncthreads();
  {
    float a0=0.f,a1=0.f,a2=0.f,a3=0.f;
    for (int i=0;i<HID;i+=4){
      a0 = fmaf(qe[i+0], w1[(i+0)*HS+t], a0);
      a1 = fmaf(qe[i+1], w1[(i+1)*HS+t], a1);
      a2 = fmaf(qe[i+2], w1[(i+2)*HS+t], a2);
      a3 = fmaf(qe[i+3], w1[(i+3)*HS+t], a3);
    }
    float acc = b1[t] + (a0+a1) + (a2+a3);
    s1[t] = acc / (1.f + expf(-acc));
  }
  __syncthreads();
  {
    float a0=0.f,a1=0.f,a2=0.f,a3=0.f;
    for (int i=0;i<HS;i+=4){
      a0 = fmaf(s1[i+0], w2[(i+0)*HS+t], a0);
      a1 = fmaf(s1[i+1], w2[(i+1)*HS+t], a1);
      a2 = fmaf(s1[i+2], w2[(i+2)*HS+t], a2);
      a3 = fmaf(s1[i+3], w2[(i+3)*HS+t], a3);
    }
    qh[t] = b2[t] + (a0+a1) + (a2+a3);
  }
  __syncthreads();
  for (int idx=t; idx<NH*HID; idx+=blockDim.x){
    int e = idx >> 8, ch = idx & 255;
    const float* wk = w_kv + (size_t)ch*1024 + e*128;   // k-half: cols [e*128, e*128+64)
    float a0=0.f,a1=0.f,a2=0.f,a3=0.f;
    for (int d=0; d<HD; d+=4){
      a0 = fmaf(qh[e*HD+d+0], wk[d+0], a0);
      a1 = fmaf(qh[e*HD+d+1], wk[d+1], a1);
      a2 = fmaf(qh[e*HD+d+2], wk[d+2], a2);
      a3 = fmaf(qh[e*HD+d+3], wk[d+3], a3);
    }
    g_u[b][e][ch] = ((a0+a1)+(a2+a3)) * rms_w[ch] * 0.125f;
  }
}

// ---------------- main fused kernel: one block per (b, h) row of 32 pixels
// smem layout (floats):
//  [0,256)        rms_sm
//  [256,2304)     ur_sm   [ch][e]
//  [2304,2560)    rinv_sm [n][w]
//  [2560,4608)    attn_sm [e][n][w]   (dots written here first, softmaxed in place)
//  [4608,12800)   cn_sm   [n][cc][w]  (pass-2 normalized c chunk)       \ aliased by
//  [12800,20992)  g_sm    [e][cc][w]                                    / wout_sm [64][256]
//  [20992,37888)  h_sm    [ed][w] with row stride 33 (pad kills write conflicts)
__global__ __launch_bounds__(256) void main_kernel(const float* __restrict__ c,
    const float* __restrict__ rms_w, const float* __restrict__ w_kv,
    const float* __restrict__ w_out, const float* __restrict__ b_out,
    float* __restrict__ out)
{
  extern __shared__ float sm[];
  float* rms_sm  = sm;
  float* ur_sm   = sm + 256;
  float* rinv_sm = sm + 2304;
  float* attn_sm = sm + 2560;
  float* cn_sm   = sm + 4608;
  float* g_sm    = sm + 12800;
  float* h_sm    = sm + 20992;
  float* wout_sm = sm + 4608;   // alias cn_sm+g_sm (16384 floats)

  const int t  = threadIdx.x;
  const int bx = blockIdx.x;
  const int b  = bx >> 5, hrow = bx & 31;
  const int w  = t & 31;
  const int n  = t >> 5;        // warp id; reused as e / ccg / og in later phases

  // load ur (transposed) and rms_w
  if (t < 256) rms_sm[t] = rms_w[t];
  {
    int ch = t;
    #pragma unroll
    for (int e=0;e<NH;e++) ur_sm[ch*NH + e] = g_u[b][e][ch];
  }
  __syncthreads();

  const float* cp = c + ((size_t)(b*NTOK + n)*HID)*1024 + hrow*32 + w;

  // ---- pass 1: stream c once; sum of squares + 8 head dots simultaneously
  float ss = 0.f;
  unsigned long long s2[4];
  s2[0]=s2[1]=s2[2]=s2[3]=0ull;
  const unsigned long long* urp = reinterpret_cast<const unsigned long long*>(ur_sm);
  #pragma unroll 4
  for (int ch=0; ch<HID; ch++){
    float x = __ldg(cp + (size_t)ch*1024);
    unsigned long long xd = pk2(x,x);
    ss = fmaf(x,x,ss);
    s2[0] = f2fma(xd, urp[ch*4+0], s2[0]);
    s2[1] = f2fma(xd, urp[ch*4+1], s2[1]);
    s2[2] = f2fma(xd, urp[ch*4+2], s2[2]);
    s2[3] = f2fma(xd, urp[ch*4+3], s2[3]);
  }
  float rinv = rsqrtf(ss*(1.f/256.f) + 1e-6f);
  rinv_sm[n*32+w] = rinv;
  #pragma unroll
  for (int j=0;j<4;j++){
    float lo,hi; upk2(s2[j],lo,hi);
    attn_sm[(2*j  )*256 + n*32 + w] = lo*rinv;
    attn_sm[(2*j+1)*256 + n*32 + w] = hi*rinv;
  }
  __syncthreads();

  // ---- softmax over n: thread (e = n-slot, w)
  {
    int e = n;
    float d[8], m = -1e30f;
    #pragma unroll
    for (int i=0;i<8;i++){ d[i] = attn_sm[e*256 + i*32 + w]; m = fmaxf(m,d[i]); }
    float ssum = 0.f;
    #pragma unroll
    for (int i=0;i<8;i++){ d[i] = expf(d[i]-m); ssum += d[i]; }
    float inv = 1.f/ssum;
    #pragma unroll
    for (int i=0;i<8;i++) attn_sm[e*256 + i*32 + w] = d[i]*inv;
  }
  __syncthreads();

  // ---- pass 2: chunked over channels; g in smem, h in registers (lane owns d-pair, packed over w-pairs)
  unsigned long long ha[16], hb[16];
  #pragma unroll
  for (int i=0;i<16;i++){ ha[i]=0ull; hb[i]=0ull; }
  const int e = n;
  const int lane = w;
  const float2* wvp = reinterpret_cast<const float2*>(w_kv + e*128 + 64 + 2*lane); // v-half

  for (int kc=0; kc<8; kc++){
    const int ch0 = kc*32;
    // stage normalized c chunk
    {
      float rv = rinv_sm[n*32+w];
      #pragma unroll 4
      for (int cc=0; cc<32; cc++){
        float x = __ldg(cp + (size_t)(ch0+cc)*1024);
        cn_sm[n*1024 + cc*32 + w] = x * rv * rms_sm[ch0+cc];
      }
    }
    __syncthreads();
    // g[e][cc][w] = sum_n attn[e][n][w] * cn[n][cc][w]; thread (ccg = n-slot, w) does 4 cc, all e
    {
      int ccg = n;
      float ga[8][4];
      #pragma unroll
      for (int i=0;i<8;i++){
        #pragma unroll
        for (int j2=0;j2<4;j2++) ga[i][j2] = 0.f;
      }
      #pragma unroll
      for (int nn=0; nn<8; nn++){
        float a[8];
        #pragma unroll
        for (int ee=0;ee<8;ee++) a[ee] = attn_sm[ee*256 + nn*32 + w];
        #pragma unroll
        for (int j2=0;j2<4;j2++){
          float cv = cn_sm[nn*1024 + (ccg*4+j2)*32 + w];
          #pragma unroll
          for (int ee=0;ee<8;ee++) ga[ee][j2] = fmaf(a[ee], cv, ga[ee][j2]);
        }
      }
      #pragma unroll
      for (int ee=0;ee<8;ee++){
        #pragma unroll
        for (int j2=0;j2<4;j2++)
          g_sm[ee*1024 + (ccg*4+j2)*32 + w] = ga[ee][j2];
      }
    }
    __syncthreads();
    // h phase: warp=e, lane owns d-pair (2l, 2l+1), 16 w-pair packed accumulators each
    #pragma unroll 2
    for (int cc=0; cc<32; cc++){
      float2 wv = __ldg(wvp + (size_t)(ch0+cc)*512);
      unsigned long long w0 = pk2(wv.x, wv.x);
      unsigned long long w1p = pk2(wv.y, wv.y);
      const unsigned long long* gp = reinterpret_cast<const unsigned long long*>(g_sm + e*1024 + cc*32);
      #pragma unroll
      for (int wp=0; wp<16; wp++){
        unsigned long long g2 = gp[wp];
        ha[wp] = f2fma(w0,  g2, ha[wp]);
        hb[wp] = f2fma(w1p, g2, hb[wp]);
      }
    }
    __syncthreads();
  }

  // write h to smem (row stride 33 to avoid 32-way STS conflicts)
  {
    int r0 = e*64 + 2*lane;
    #pragma unroll
    for (int wp=0; wp<16; wp++){
      float lo,hi;
      upk2(ha[wp],lo,hi);
      h_sm[r0*33 + 2*wp  ] = lo;
      h_sm[r0*33 + 2*wp+1] = hi;
      upk2(hb[wp],lo,hi);
      h_sm[(r0+1)*33 + 2*wp  ] = lo;
      h_sm[(r0+1)*33 + 2*wp+1] = hi;
    }
  }
  __syncthreads();

  // ---- epilogue: out[o][w] = sum_ed h[ed][w] * w_out[ed][o]; warp=og owns o range [og*32, og*32+32)
  unsigned long long o2[16];
  #pragma unroll
  for (int i=0;i<16;i++) o2[i]=0ull;
  const int og = n;
  for (int edc=0; edc<8; edc++){
    // stage w_out chunk [64][256] into aliased smem
    {
      const float4* src = reinterpret_cast<const float4*>(w_out + (size_t)edc*64*256);
      float4* dst = reinterpret_cast<float4*>(wout_sm);
      #pragma unroll
      for (int r=0; r<16; r++)
        dst[r*256 + t] = __ldg(src + r*256 + t);
    }
    __syncthreads();
    #pragma unroll 4
    for (int ed=0; ed<64; ed++){
      float hv = h_sm[(edc*64+ed)*33 + w];
      unsigned long long hd = pk2(hv,hv);
      const unsigned long long* wp2 = reinterpret_cast<const unsigned long long*>(wout_sm + ed*256 + og*32);
      #pragma unroll
      for (int op=0; op<16; op++)
        o2[op] = f2fma(hd, wp2[op], o2[op]);
    }
    __syncthreads();
  }

  // final store: out[b][o][h][w] (+ b_out)
  size_t obase = ((size_t)b*256)*1024 + (size_t)hrow*32 + w;
  #pragma unroll
  for (int op=0; op<16; op++){
    float lo,hi; upk2(o2[op],lo,hi);
    int oo = og*32 + 2*op;
    out[obase + (size_t)oo*1024]     = lo + __ldg(b_out+oo);
    out[obase + (size_t)(oo+1)*1024] = hi + __ldg(b_out+oo+1);
  }
}

extern "C" void kernel_launch(void* const* d_in, const int* in_sizes, int n_in,
                              void* d_out, int out_size) {
  const int*   q     = (const int*)  d_in[0];
  const float* c     = (const float*)d_in[1];
  const float* rms_w = (const float*)d_in[2];
  const float* emb   = (const float*)d_in[3];
  const float* w1    = (const float*)d_in[4];
  const float* b1    = (const float*)d_in[5];
  const float* w2    = (const float*)d_in[6];
  const float* b2    = (const float*)d_in[7];
  const float* w_kv  = (const float*)d_in[8];
  const float* w_out = (const float*)d_in[9];
  const float* b_out = (const float*)d_in[10];
  float* out = (float*)d_out;

  setup_kernel<<<8, 512>>>(q, emb, w1, b1, w2, b2, w_kv, rms_w);

  int smem_bytes = 37888 * 4;  // 148 KB
  cudaFuncSetAttribute(main_kernel, cudaFuncAttributeMaxDynamicSharedMemorySize, smem_bytes);
  main_kernel<<<256, 256, smem_bytes>>>(c, rms_w, w_kv, w_out, b_out, out);
}

// round 6
// speedup vs baseline: 1.8871x; 1.8871x over previous
#include <cuda_runtime.h>
#include <cstdint>
#include <cstdio>

#define HID 256
#define HS  512
#define NH  8
#define HD  64
#define NTOK 8
#define BB  8

// Per-batch folded query vectors: u[b][e][ch] = (sum_d qh[b,e,d]*w_kv[ch, e*128+d]) * rms_w[ch] * 0.125
__device__ float g_u[BB][NH][HID];

static __device__ __forceinline__ unsigned long long pk2(float lo, float hi){
  unsigned long long r; asm("mov.b64 %0, {%1,%2};" : "=l"(r) : "f"(lo), "f"(hi)); return r;
}
static __device__ __forceinline__ void upk2(unsigned long long v, float& lo, float& hi){
  asm("mov.b64 {%0,%1}, %2;" : "=f"(lo), "=f"(hi) : "l"(v));
}
static __device__ __forceinline__ unsigned long long f2fma(unsigned long long a, unsigned long long b, unsigned long long c){
  unsigned long long d; asm("fma.rn.f32x2 %0, %1, %2, %3;" : "=l"(d) : "l"(a), "l"(b), "l"(c)); return d;
}

// ---------------- setup: qh = silu(emb[q]@w1+b1)@w2+b2 ; u = (w_kv_k,e @ qh_e) * rms_w * scale
__global__ void setup_kernel(const int* __restrict__ q, const float* __restrict__ emb,
                             const float* __restrict__ w1, const float* __restrict__ b1,
                             const float* __restrict__ w2, const float* __restrict__ b2,
                             const float* __restrict__ w_kv, const float* __restrict__ rms_w)
{
  __shared__ float qe[HID], s1[HS], qh[HS];
  int b = blockIdx.x, t = threadIdx.x;
  if (t < HID) qe[t] = emb[(size_t)q[b]*HID + t];
  __syncthreads();
  {
    float a0=0.f,a1=0.f,a2=0.f,a3=0.f;
    for (int i=0;i<HID;i+=4){
      a0 = fmaf(qe[i+0], w1[(i+0)*HS+t], a0);
      a1 = fmaf(qe[i+1], w1[(i+1)*HS+t], a1);
      a2 = fmaf(qe[i+2], w1[(i+2)*HS+t], a2);
      a3 = fmaf(qe[i+3], w1[(i+3)*HS+t], a3);
    }
    float acc = b1[t] + (a0+a1) + (a2+a3);
    s1[t] = acc / (1.f + expf(-acc));
  }
  __syncthreads();
  {
    float a0=0.f,a1=0.f,a2=0.f,a3=0.f;
    for (int i=0;i<HS;i+=4){
      a0 = fmaf(s1[i+0], w2[(i+0)*HS+t], a0);
      a1 = fmaf(s1[i+1], w2[(i+1)*HS+t], a1);
      a2 = fmaf(s1[i+2], w2[(i+2)*HS+t], a2);
      a3 = fmaf(s1[i+3], w2[(i+3)*HS+t], a3);
    }
    qh[t] = b2[t] + (a0+a1) + (a2+a3);
  }
  __syncthreads();
  for (int idx=t; idx<NH*HID; idx+=blockDim.x){
    int e = idx >> 8, ch = idx & 255;
    const float* wk = w_kv + (size_t)ch*1024 + e*128;   // k-half: cols [e*128, e*128+64)
    float a0=0.f,a1=0.f,a2=0.f,a3=0.f;
    for (int d=0; d<HD; d+=4){
      a0 = fmaf(qh[e*HD+d+0], wk[d+0], a0);
      a1 = fmaf(qh[e*HD+d+1], wk[d+1], a1);
      a2 = fmaf(qh[e*HD+d+2], wk[d+2], a2);
      a3 = fmaf(qh[e*HD+d+3], wk[d+3], a3);
    }
    g_u[b][e][ch] = ((a0+a1)+(a2+a3)) * rms_w[ch] * 0.125f;
  }
}

// ---------------- main fused kernel: one block per (b, hrow) row of 32 pixels
// smem layout (floats), total 20992 floats = 84KB -> 2 blocks/SM:
//  [0,256)        rms_sm
//  [256,2304)     ur_sm   [ch][e]
//  [2304,2560)    rinv_sm [n][w]
//  [2560,4608)    attn_sm [e][n][w]
//  [4608,12800)   cn_sm   [n][cc][w]   \  aliased after the chunk loop by
//  [12800,20992)  g_sm    [e][cc][w]   /  h_sm [512 ed][32 w] (swizzled cols)
__global__ __launch_bounds__(256, 2) void main_kernel(const float* __restrict__ c,
    const float* __restrict__ rms_w, const float* __restrict__ w_kv,
    const float* __restrict__ w_out, const float* __restrict__ b_out,
    float* __restrict__ out)
{
  extern __shared__ float sm[];
  float* rms_sm  = sm;
  float* ur_sm   = sm + 256;
  float* rinv_sm = sm + 2304;
  float* attn_sm = sm + 2560;
  float* cn_sm   = sm + 4608;
  float* g_sm    = sm + 12800;
  float* h_sm    = sm + 4608;   // alias cn_sm+g_sm (16384 floats, used after chunk loop)

  const int t  = threadIdx.x;
  const int bx = blockIdx.x;
  const int b  = bx >> 5, hrow = bx & 31;
  const int w  = t & 31;
  const int n  = t >> 5;        // warp id; reused as e / ccg later
  const int lane = w;

  // load ur (transposed) and rms_w
  rms_sm[t] = rms_w[t];
  {
    int ch = t;
    #pragma unroll
    for (int e=0;e<NH;e++) ur_sm[ch*NH + e] = g_u[b][e][ch];
  }
  __syncthreads();

  const float* cp = c + ((size_t)(b*NTOK + n)*HID)*1024 + hrow*32 + w;

  // ---- pass 1: stream c once; sum of squares + 8 head dots simultaneously
  float ss = 0.f;
  unsigned long long s2[4];
  s2[0]=s2[1]=s2[2]=s2[3]=0ull;
  const unsigned long long* urp = reinterpret_cast<const unsigned long long*>(ur_sm);
  #pragma unroll 4
  for (int ch=0; ch<HID; ch++){
    float x = __ldg(cp + (size_t)ch*1024);
    unsigned long long xd = pk2(x,x);
    ss = fmaf(x,x,ss);
    s2[0] = f2fma(xd, urp[ch*4+0], s2[0]);
    s2[1] = f2fma(xd, urp[ch*4+1], s2[1]);
    s2[2] = f2fma(xd, urp[ch*4+2], s2[2]);
    s2[3] = f2fma(xd, urp[ch*4+3], s2[3]);
  }
  float rinv = rsqrtf(ss*(1.f/256.f) + 1e-6f);
  rinv_sm[n*32+w] = rinv;
  #pragma unroll
  for (int j=0;j<4;j++){
    float lo,hi; upk2(s2[j],lo,hi);
    attn_sm[(2*j  )*256 + n*32 + w] = lo*rinv;
    attn_sm[(2*j+1)*256 + n*32 + w] = hi*rinv;
  }
  __syncthreads();

  // ---- softmax over n: thread (e = n-slot, w)
  {
    int e = n;
    float d[8], m = -1e30f;
    #pragma unroll
    for (int i=0;i<8;i++){ d[i] = attn_sm[e*256 + i*32 + w]; m = fmaxf(m,d[i]); }
    float ssum = 0.f;
    #pragma unroll
    for (int i=0;i<8;i++){ d[i] = __expf(d[i]-m); ssum += d[i]; }
    float inv = 1.f/ssum;
    #pragma unroll
    for (int i=0;i<8;i++) attn_sm[e*256 + i*32 + w] = d[i]*inv;
  }
  __syncthreads();

  // ---- pass 2: chunked over channels; g in smem; h accumulated in registers
  // h-phase tile: warp = e; thread owns d in [d0, d0+8) (as 4 native u64 d-pairs)
  // and 8 strided w values w_k = wbase + 4k.
  const int e  = n;
  const int d0 = (lane & 7) * 8;
  const int wbase = lane >> 3;      // 0..3
  unsigned long long hacc[4][8];
  #pragma unroll
  for (int i=0;i<4;i++){
    #pragma unroll
    for (int k=0;k<8;k++) hacc[i][k]=0ull;
  }
  // v-half of w_kv, viewed as ulonglong2 (16B = 4 floats). Row stride of w_kv
  // is 1024 floats = 4096 bytes = 256 ulonglong2 per channel.  (R4 bug: was *64)
  const ulonglong2* wvp_base =
      reinterpret_cast<const ulonglong2*>(w_kv + e*128 + 64 + d0);

  for (int kc=0; kc<8; kc++){
    const int ch0 = kc*32;
    // stage normalized c chunk: thread (n, w)
    {
      float rv = rinv_sm[n*32+w];
      #pragma unroll 4
      for (int cc=0; cc<32; cc++){
        float x = __ldg(cp + (size_t)(ch0+cc)*1024);
        cn_sm[n*1024 + cc*32 + w] = x * rv * rms_sm[ch0+cc];
      }
    }
    __syncthreads();
    // g[e][cc][w] = sum_n attn[e][n][w] * cn[n][cc][w]; thread (ccg = n-slot, w) does 4 cc, all e
    {
      int ccg = n;
      float ga[8][4];
      #pragma unroll
      for (int i=0;i<8;i++){
        #pragma unroll
        for (int j2=0;j2<4;j2++) ga[i][j2] = 0.f;
      }
      #pragma unroll
      for (int nn=0; nn<8; nn++){
        float a[8];
        #pragma unroll
        for (int ee=0;ee<8;ee++) a[ee] = attn_sm[ee*256 + nn*32 + w];
        #pragma unroll
        for (int j2=0;j2<4;j2++){
          float cv = cn_sm[nn*1024 + (ccg*4+j2)*32 + w];
          #pragma unroll
          for (int ee=0;ee<8;ee++) ga[ee][j2] = fmaf(a[ee], cv, ga[ee][j2]);
        }
      }
      #pragma unroll
      for (int ee=0;ee<8;ee++){
        #pragma unroll
        for (int j2=0;j2<4;j2++)
          g_sm[ee*1024 + (ccg*4+j2)*32 + w] = ga[ee][j2];
      }
    }
    __syncthreads();
    // h-phase: wv as native packed d-pairs (no pk), g broadcast-dup per w
    {
      const float* gbase = g_sm + e*1024 + wbase;
      #pragma unroll 2
      for (int cc=0; cc<32; cc++){
        const int ch = ch0 + cc;
        ulonglong2 wv0 = __ldg(wvp_base + (size_t)ch*256);
        ulonglong2 wv1 = __ldg(wvp_base + (size_t)ch*256 + 1);
        const float* gp = gbase + cc*32;
        #pragma unroll
        for (int k=0;k<8;k++){
          float gv = gp[4*k];
          unsigned long long gd = pk2(gv,gv);
          hacc[0][k] = f2fma(wv0.x, gd, hacc[0][k]);
          hacc[1][k] = f2fma(wv0.y, gd, hacc[1][k]);
          hacc[2][k] = f2fma(wv1.x, gd, hacc[2][k]);
          hacc[3][k] = f2fma(wv1.y, gd, hacc[3][k]);
        }
      }
    }
    __syncthreads();   // protect cn_sm/g_sm before next chunk (and before h alias below)
  }

  // ---- write h to aliased smem with column swizzle ((w + (ed>>1)) & 31): conflict-free
  {
    #pragma unroll
    for (int dp=0; dp<4; dp++){
      int ed = e*64 + d0 + 2*dp;        // even
      int sw = (ed >> 1);
      #pragma unroll
      for (int k=0;k<8;k++){
        float lo,hi; upk2(hacc[dp][k],lo,hi);
        int w_ = wbase + 4*k;
        h_sm[ ed   *32 + ((w_ + sw) & 31)] = lo;
        h_sm[(ed+1)*32 + ((w_ + sw) & 31)] = hi;
      }
    }
  }
  __syncthreads();

  // ---- epilogue: out[o][w] = sum_ed h[ed][w] * w_out[ed][o]
  // thread tile: 16 o (8 native u64 o-pairs from LDG128) x 2 w
  {
    const int o0  = n*32 + (lane >> 4)*16;
    const int wj0 = (lane & 15)*2;
    unsigned long long oacc[8][2];
    #pragma unroll
    for (int i=0;i<8;i++){ oacc[i][0]=0ull; oacc[i][1]=0ull; }

    #pragma unroll 2
    for (int ed=0; ed<512; ed++){
      const ulonglong2* wrow = reinterpret_cast<const ulonglong2*>(w_out + (size_t)ed*256 + o0);
      ulonglong2 q0 = __ldg(wrow + 0);
      ulonglong2 q1 = __ldg(wrow + 1);
      ulonglong2 q2 = __ldg(wrow + 2);
      ulonglong2 q3 = __ldg(wrow + 3);
      int sw = (ed >> 1);
      float h0 = h_sm[ed*32 + ((wj0   + sw) & 31)];
      float h1 = h_sm[ed*32 + ((wj0+1 + sw) & 31)];
      unsigned long long hd0 = pk2(h0,h0);
      unsigned long long hd1 = pk2(h1,h1);
      oacc[0][0]=f2fma(q0.x,hd0,oacc[0][0]); oacc[0][1]=f2fma(q0.x,hd1,oacc[0][1]);
      oacc[1][0]=f2fma(q0.y,hd0,oacc[1][0]); oacc[1][1]=f2fma(q0.y,hd1,oacc[1][1]);
      oacc[2][0]=f2fma(q1.x,hd0,oacc[2][0]); oacc[2][1]=f2fma(q1.x,hd1,oacc[2][1]);
      oacc[3][0]=f2fma(q1.y,hd0,oacc[3][0]); oacc[3][1]=f2fma(q1.y,hd1,oacc[3][1]);
      oacc[4][0]=f2fma(q2.x,hd0,oacc[4][0]); oacc[4][1]=f2fma(q2.x,hd1,oacc[4][1]);
      oacc[5][0]=f2fma(q2.y,hd0,oacc[5][0]); oacc[5][1]=f2fma(q2.y,hd1,oacc[5][1]);
      oacc[6][0]=f2fma(q3.x,hd0,oacc[6][0]); oacc[6][1]=f2fma(q3.x,hd1,oacc[6][1]);
      oacc[7][0]=f2fma(q3.y,hd0,oacc[7][0]); oacc[7][1]=f2fma(q3.y,hd1,oacc[7][1]);
    }

    // bias
    float bo[16];
    {
      const float4* bp = reinterpret_cast<const float4*>(b_out + o0);
      #pragma unroll
      for (int i=0;i<4;i++){
        float4 v = __ldg(bp + i);
        bo[4*i+0]=v.x; bo[4*i+1]=v.y; bo[4*i+2]=v.z; bo[4*i+3]=v.w;
      }
    }
    const size_t pbase = (size_t)b*256*1024 + (size_t)hrow*32;
    #pragma unroll
    for (int op=0; op<8; op++){
      #pragma unroll
      for (int j=0;j<2;j++){
        float lo,hi; upk2(oacc[op][j],lo,hi);
        int oa = o0 + 2*op;
        out[pbase + (size_t)oa*1024     + wj0 + j] = lo + bo[2*op];
        out[pbase + (size_t)(oa+1)*1024 + wj0 + j] = hi + bo[2*op+1];
      }
    }
  }
}

extern "C" void kernel_launch(void* const* d_in, const int* in_sizes, int n_in,
                              void* d_out, int out_size) {
  const int*   q     = (const int*)  d_in[0];
  const float* c     = (const float*)d_in[1];
  const float* rms_w = (const float*)d_in[2];
  const float* emb   = (const float*)d_in[3];
  const float* w1    = (const float*)d_in[4];
  const float* b1    = (const float*)d_in[5];
  const float* w2    = (const float*)d_in[6];
  const float* b2    = (const float*)d_in[7];
  const float* w_kv  = (const float*)d_in[8];
  const float* w_out = (const float*)d_in[9];
  const float* b_out = (const float*)d_in[10];
  float* out = (float*)d_out;

  setup_kernel<<<8, 512>>>(q, emb, w1, b1, w2, b2, w_kv, rms_w);

  int smem_bytes = 20992 * 4;  // 84KB -> 2 blocks/SM
  cudaFuncSetAttribute(main_kernel, cudaFuncAttributeMaxDynamicSharedMemorySize, smem_bytes);
  main_kernel<<<256, 256, smem_bytes>>>(c, rms_w, w_kv, w_out, b_out, out);
}